// round 10
// baseline (speedup 1.0000x reference)
#include <cuda_runtime.h>
#include <math.h>

#define NB 16
#define NC 64
#define NH 128
#define NW 128
#define PI2 6.283185307179586f

// ---------------- scratch ------------------------------------------------
__device__ float2 d_X [NB*256*64];        // [b][kl][i]
__device__ float2 d_Y [NB*256*64];        // [b][kl][o]
__device__ float  d_Z1[NB*NH*64*32];      // [b][h][o][0..15 zr |16..31 zi] (tf32)
__device__ float2 d_Wt[256*64*64];        // [kl][i*64+o]
__device__ float  d_proj[NB*NC];
__device__ float  d_Eout [32*128];        // [n][w]: n<16 cos, n>=16 -sin (tf32)
__device__ float  d_EoutT[128*32];        // [w][n]  transposed copy
__device__ float2 d_twdp[128];            // e^{+i 2pi m/128}

// ---------------- helpers ------------------------------------------------
__device__ __forceinline__ unsigned tf32u(float f) {
    unsigned r; asm("cvt.rna.tf32.f32 %0, %1;" : "=r"(r) : "f"(f)); return r;
}
__device__ __forceinline__ float tf32f(float f) { return __uint_as_float(tf32u(f)); }
__device__ __forceinline__ void mma_tf32(float* c,
    unsigned a0, unsigned a1, unsigned a2, unsigned a3, unsigned b0, unsigned b1) {
    asm volatile(
        "mma.sync.aligned.m16n8k8.row.col.f32.tf32.tf32.f32 "
        "{%0,%1,%2,%3}, {%4,%5,%6,%7}, {%8,%9}, {%0,%1,%2,%3};"
        : "+f"(c[0]), "+f"(c[1]), "+f"(c[2]), "+f"(c[3])
        : "r"(a0), "r"(a1), "r"(a2), "r"(a3), "r"(b0), "r"(b1));
}
__device__ __forceinline__ unsigned s2u(const void* p) {
    unsigned a;
    asm("{ .reg .u64 t; cvta.to.shared.u64 t, %1; cvt.u32.u64 %0, t; }" : "=r"(a) : "l"(p));
    return a;
}
__device__ __forceinline__ void ldsm4(unsigned &r0, unsigned &r1, unsigned &r2,
                                      unsigned &r3, unsigned a) {
    asm volatile("ldmatrix.sync.aligned.m8n8.x4.shared.b16 {%0,%1,%2,%3}, [%4];"
        : "=r"(r0), "=r"(r1), "=r"(r2), "=r"(r3) : "r"(a));
}
__device__ __forceinline__ void cpa16(unsigned dst, const void* src) {
    asm volatile("cp.async.ca.shared.global [%0], [%1], 16;" :: "r"(dst), "l"(src));
}
__device__ __forceinline__ void cpa_commit() {
    asm volatile("cp.async.commit_group;");
}
__device__ __forceinline__ void cpa_wait_all() {
    asm volatile("cp.async.wait_group 0;" ::: "memory");
}
template<int N>
__device__ __forceinline__ void cpa_wait_n() {
    asm volatile("cp.async.wait_group %0;" :: "n"(N) : "memory");
}

// ---------------- precompute ---------------------------------------------
__global__ void k_prep() {
    int t = threadIdx.x;                       // 256
    for (int idx = t; idx < 4096; idx += 256) {
        int r = idx >> 7, w = idx & 127;
        int l = r & 15;
        float s, c;
        sincosf(PI2 * (float)((l*w) & 127) * (1.f/128.f), &s, &c);
        float v = tf32f(r < 16 ? c : -s);
        d_Eout[idx] = v;
        d_EoutT[w*32 + r] = v;
    }
    if (t < 128) {
        float s, c; sincosf(PI2 * t * (1.f/128.f), &s, &c);
        d_twdp[t] = make_float2(c, s);
    }
}

// ---------------- temb projection ---------------------------------------
__global__ void k_proj(const float* __restrict__ temb,
                       const float* __restrict__ twm,
                       const float* __restrict__ tbv) {
    __shared__ float s_silu[512];
    int b = blockIdx.x, cg = blockIdx.y, t = threadIdx.x;   // 256 threads
    for (int j = t; j < 512; j += 256) {
        float v = temb[b*512 + j];
        s_silu[j] = v / (1.f + __expf(-v));
    }
    __syncthreads();
    int w = t >> 5, lane = t & 31;
    int c = cg*8 + w;
    float acc = 0.f;
    #pragma unroll 4
    for (int j = lane; j < 512; j += 32) acc += s_silu[j] * twm[c*512 + j];
    #pragma unroll
    for (int off = 16; off > 0; off >>= 1)
        acc += __shfl_xor_sync(0xffffffffu, acc, off);
    if (lane == 0) d_proj[b*64 + c] = acc + tbv[c];
}

// ---------------- weight transpose: [i,o,k,l] -> [kl][i*64+o] ------------
__global__ void k_wt(const float* __restrict__ wr, const float* __restrict__ wi) {
    __shared__ float tr[32][33], ti[32][33];
    int kl0 = blockIdx.x * 32, io0 = blockIdx.y * 32;
    for (int r = threadIdx.y; r < 32; r += 8) {
        tr[r][threadIdx.x] = wr[(io0 + r)*256 + kl0 + threadIdx.x];
        ti[r][threadIdx.x] = wi[(io0 + r)*256 + kl0 + threadIdx.x];
    }
    __syncthreads();
    for (int r = threadIdx.y; r < 32; r += 8) {
        d_Wt[(kl0 + r)*4096 + io0 + threadIdx.x] =
            make_float2(tr[threadIdx.x][r], ti[threadIdx.x][r]);
    }
}

// ---------------- fused forward DFT (one block = one bi) -----------------
// Stage 1 (x4 hq, pipelined): P[n][h] = sum_w x[h,w] * E[n,w]  -> smem
// Stage 2: X[k,l] = (1/128) * combine( E[a,h] @ P[p,h] )
#define FWD_SMEM ((32*132 + 2*32*132 + 32*132)*4)
__global__ __launch_bounds__(128) void k_fwd(const float* __restrict__ x) {
    extern __shared__ float sm[];
    float* Es = sm;                    // [32 n][132 w|h]
    float* xs = sm + 32*132;           // [2 stage][32 h][132 w]
    float* Pb = sm + 3*32*132;         // [32 n][132 h]
    int t = threadIdx.x, lane = t & 31, warp = t >> 5;
    int bi = blockIdx.x, b = bi >> 6, ci = bi & 63;

    unsigned EsA = s2u(Es), xsA = s2u(xs), PbA = s2u(Pb);
    const float* xp = x + (size_t)bi * 16384;

    // prologue: E + x tile 0  (group 0)
    for (int idx = t; idx < 1024; idx += 128) {
        int r = idx >> 5, c4 = idx & 31;
        cpa16(EsA + (r*132 + c4*4)*4, d_Eout + r*128 + c4*4);
    }
    for (int idx = t; idx < 1024; idx += 128) {
        int hh = idx >> 5, w4 = idx & 31;
        cpa16(xsA + (hh*132 + w4*4)*4, xp + hh*128 + w4*4);
    }
    cpa_commit();

    int qr = lane >> 2, qc = lane & 3, lr = lane & 7, lg = lane >> 3;
    int m0 = (warp & 1)*16, n0 = (warp >> 1)*16;

    // ---- stage 1 loop over 4 hq tiles, double-buffered ----
    #pragma unroll
    for (int hq = 0; hq < 4; hq++) {
        if (hq < 3) {
            unsigned dstA = xsA + ((hq+1) & 1)*4224*4;
            const float* src = xp + (hq+1)*4096;
            for (int idx = t; idx < 1024; idx += 128) {
                int hh = idx >> 5, w4 = idx & 31;
                cpa16(dstA + (hh*132 + w4*4)*4, src + hh*128 + w4*4);
            }
            cpa_commit();
            cpa_wait_n<1>();
        } else {
            cpa_wait_all();
        }
        __syncthreads();

        unsigned aBase = xsA + (hq & 1)*4224*4
                       + ((m0 + lr + (lg & 1)*8)*132 + (lg >> 1)*4)*4;
        unsigned bBase = EsA + ((n0 + lr + (lg >> 1)*8)*132 + (lg & 1)*4)*4;

        float acc[2][4];
        #pragma unroll
        for (int g = 0; g < 2; g++)
            #pragma unroll
            for (int j = 0; j < 4; j++) acc[g][j] = 0.f;

        #pragma unroll
        for (int kk = 0; kk < 16; kk++) {
            unsigned a0, a1, a2, a3, b0, b1, b2, b3;
            ldsm4(a0, a1, a2, a3, aBase + kk*32);
            ldsm4(b0, b1, b2, b3, bBase + kk*32);
            mma_tf32(acc[0], a0, a1, a2, a3, b0, b1);
            mma_tf32(acc[1], a0, a1, a2, a3, b2, b3);
        }
        // store P tile: n = n0+g*8+2qc+cc, h = hq*32 + m0+qr+half*8
        #pragma unroll
        for (int g = 0; g < 2; g++)
            #pragma unroll
            for (int half = 0; half < 2; half++)
                #pragma unroll
                for (int cc = 0; cc < 2; cc++)
                    Pb[(n0 + g*8 + 2*qc + cc)*132 + hq*32 + m0 + qr + half*8] =
                        tf32f(acc[g][half*2 + cc]);
        __syncthreads();
    }

    // ---- stage 2: warps 0,1 compute X (l-half per warp) ----
    if (warp < 2) {
        unsigned aB = EsA + ((lr + (lg & 1)*8)*132 + (lg >> 1)*4)*4;
        unsigned bB = PbA + ((lr + (lg >> 1)*8)*132 + (lg & 1)*4)*4;

        float acc[2][4][4];   // [m: cos/-sin][nb*2+lhalf? -> here nb fixed pairs][frag]
        #pragma unroll
        for (int m = 0; m < 2; m++)
            #pragma unroll
            for (int n = 0; n < 4; n++)
                #pragma unroll
                for (int j = 0; j < 4; j++) acc[m][n][j] = 0.f;

        #pragma unroll
        for (int kk = 0; kk < 16; kk++) {
            unsigned a[2][4];
            ldsm4(a[0][0], a[0][1], a[0][2], a[0][3], aB + kk*32);
            ldsm4(a[1][0], a[1][1], a[1][2], a[1][3], aB + 16*132*4 + kk*32);
            #pragma unroll
            for (int nb = 0; nb < 2; nb++) {       // nb0 = Pr rows, nb1 = Pi rows
                unsigned b0, b1, b2, b3;
                ldsm4(b0, b1, b2, b3, bB + nb*16*132*4 + kk*32);
                unsigned u0 = (warp == 0) ? b0 : b2;
                unsigned u1 = (warp == 0) ? b1 : b3;
                #pragma unroll
                for (int m = 0; m < 2; m++)
                    mma_tf32(acc[m][nb*2 + warp], a[m][0], a[m][1], a[m][2], a[m][3], u0, u1);
            }
        }
        // combine: xr = cos·Pr + sin·Pi = acc[0][Pr] - acc[1][Pi]
        //          xi = cos·Pi - sin·Pr = acc[0][Pi] + acc[1][Pr]
        #pragma unroll
        for (int half = 0; half < 2; half++)
            #pragma unroll
            for (int cc = 0; cc < 2; cc++) {
                int k = qr + half*8;
                int l = warp*8 + 2*qc + cc;
                int j = half*2 + cc;
                float xr = (acc[0][warp][j]     - acc[1][2 + warp][j]) * (1.f/128.f);
                float xi = (acc[0][2 + warp][j] + acc[1][warp][j])     * (1.f/128.f);
                d_X[((size_t)b*256 + k*16 + l)*64 + ci] = make_float2(xr, xi);
            }
    }
}

// ---------------- per-mode channel mixing (o-split x4) -------------------
__global__ __launch_bounds__(256) void k_mix() {
    __shared__ float2 Ws[64*16];    // [i][ol]
    __shared__ float2 Xs[16*64];    // [b][i]
    int kl = blockIdx.x, oq = blockIdx.y, t = threadIdx.x;
    for (int idx = t; idx < 1024; idx += 256)
        Ws[idx] = d_Wt[kl*4096 + (idx >> 4)*64 + oq*16 + (idx & 15)];
    for (int idx = t; idx < 1024; idx += 256)
        Xs[idx] = d_X[((size_t)(idx >> 6)*256 + kl)*64 + (idx & 63)];
    __syncthreads();
    int ol = t & 15, b = t >> 4;
    float yr = 0.f, yi = 0.f;
    #pragma unroll 8
    for (int i = 0; i < 64; i++) {
        float2 xv = Xs[b*64 + i];
        float2 wv = Ws[i*16 + ol];
        yr += xv.x*wv.x - xv.y*wv.y;
        yi += xv.x*wv.y + xv.y*wv.x;
    }
    d_Y[((size_t)b*256 + kl)*64 + oq*16 + ol] = make_float2(yr, yi);
}

// ---------------- inverse stage 1 (over k) -------------------------------
__global__ __launch_bounds__(256) void k_invh() {
    __shared__ float2 Ys[256];
    __shared__ float2 twd[128];
    int t = threadIdx.x, bo = blockIdx.x;
    int b = bo >> 6, o = bo & 63;
    if (t < 128) twd[t] = d_twdp[t];
    Ys[t] = d_Y[((size_t)b*256 + t)*64 + o];
    __syncthreads();
    #pragma unroll
    for (int rep = 0; rep < 8; rep++) {
        int idx = rep*256 + t;
        int h = idx >> 4, l = idx & 15;
        float zr = 0.f, zi = 0.f;
        #pragma unroll
        for (int k = 0; k < 16; k++) {
            float2 y = Ys[k*16 + l];
            float2 e = twd[(k*h) & 127];
            zr += y.x*e.x - y.y*e.y;
            zi += y.x*e.y + y.y*e.x;
        }
        float f = (l == 0 ? 1.f : 2.f) * (1.f/128.f);
        float* zp = d_Z1 + (((size_t)b*128 + h)*64 + o)*32;
        zp[l]      = tf32f(zr*f);
        zp[16 + l] = tf32f(zi*f);
    }
}

// ---------------- fused final (w-split): C[64o,64w] = A[64,96]@B[96,64] --
#define KP 100
#define AP 100
#define OUT_SMEM ((64*KP + 64*AP + 128)*4)
__global__ __launch_bounds__(256) void k_out(const float* __restrict__ x,
                                             const float* __restrict__ bw,
                                             const float* __restrict__ bb,
                                             float* __restrict__ out) {
    extern __shared__ float sm[];
    float* Bt  = sm;               // [64 w][KP]
    float* As  = Bt + 64*KP;       // [64 o][AP]
    float* bbp = As + 64*AP;

    int t = threadIdx.x;           // 256 = 8 warps
    int b = blockIdx.x >> 7, h = blockIdx.x & 127;
    int wq = blockIdx.y;           // 0/1 -> w half

    unsigned BtA = s2u(Bt), AsA = s2u(As);

    // As cols 0..63: bw rows (raw f32, HW-truncated by mma)
    for (int idx = t; idx < 1024; idx += 256) {
        int o = idx >> 4, c4 = idx & 15;
        cpa16(AsA + (o*AP + c4*4)*4, bw + o*64 + c4*4);
    }
    // As cols 64..95: Z1 row (zr|zi, pre-rounded)
    for (int idx = t; idx < 512; idx += 256) {
        int o = idx >> 3, c4 = idx & 7;
        cpa16(AsA + (o*AP + 64 + c4*4)*4,
              d_Z1 + (((size_t)b*128 + h)*64 + o)*32 + c4*4);
    }
    // Bt cols 64..95: EoutT rows
    for (int idx = t; idx < 512; idx += 256) {
        int w = idx >> 3, c4 = idx & 7;
        cpa16(BtA + (w*KP + 64 + c4*4)*4, d_EoutT + (wq*64 + w)*32 + c4*4);
    }
    // Bt cols 0..63: x transposed (raw f32)
    for (int idx = t; idx < 1024; idx += 256) {
        int i = idx >> 4, w4 = idx & 15;
        float4 v = *(const float4*)(x + (((size_t)(b*64 + i))*128 + h)*128
                                      + wq*64 + w4*4);
        Bt[(w4*4+0)*KP + i] = v.x;
        Bt[(w4*4+1)*KP + i] = v.y;
        Bt[(w4*4+2)*KP + i] = v.z;
        Bt[(w4*4+3)*KP + i] = v.w;
    }
    if (t < 64) bbp[t] = bb[t];
    else if (t < 128) bbp[t] = d_proj[b*64 + (t - 64)];
    cpa_commit();
    cpa_wait_all();
    __syncthreads();

    int lane = t & 31, warp = t >> 5;
    int m0 = (warp & 3) * 16, n0 = (warp >> 2) * 32;
    int qr = lane >> 2, qc = lane & 3;
    int lr = lane & 7, lg = lane >> 3;

    unsigned aBase = AsA + ((m0 + lr + (lg & 1)*8)*AP + (lg >> 1)*4)*4;
    unsigned bBase = BtA + ((n0 + lr + (lg >> 1)*8)*KP + (lg & 1)*4)*4;

    float acc[4][4];
    #pragma unroll
    for (int nt = 0; nt < 4; nt++)
        #pragma unroll
        for (int j = 0; j < 4; j++) acc[nt][j] = 0.f;

    #pragma unroll
    for (int kk = 0; kk < 12; kk++) {
        unsigned a0, a1, a2, a3;
        ldsm4(a0, a1, a2, a3, aBase + kk*32);
        #pragma unroll
        for (int p = 0; p < 2; p++) {
            unsigned b0, b1, b2, b3;
            ldsm4(b0, b1, b2, b3, bBase + p*16*KP*4 + kk*32);
            mma_tf32(acc[2*p],   a0, a1, a2, a3, b0, b1);
            mma_tf32(acc[2*p+1], a0, a1, a2, a3, b2, b3);
        }
    }

    #pragma unroll
    for (int nt = 0; nt < 4; nt++) {
        #pragma unroll
        for (int half = 0; half < 2; half++) {
            int o = m0 + qr + half*8;
            float bias = bbp[o], pr = bbp[64 + o];
            float v0 = acc[nt][half*2 + 0] + bias;
            float v1 = acc[nt][half*2 + 1] + bias;
            v0 = 0.5f * v0 * (1.f + erff(v0 * 0.70710678118f)) + pr;
            v1 = 0.5f * v1 * (1.f + erff(v1 * 0.70710678118f)) + pr;
            int w = wq*64 + n0 + nt*8 + qc*2;
            *(float2*)(out + (((size_t)(b*64 + o))*128 + h)*128 + w) =
                make_float2(v0, v1);
        }
    }
}

// ---------------- launcher ----------------------------------------------
extern "C" void kernel_launch(void* const* d_in, const int* in_sizes, int n_in,
                              void* d_out, int out_size) {
    const float* x    = (const float*)d_in[0];
    const float* temb = (const float*)d_in[1];
    const float* wr   = (const float*)d_in[2];
    const float* wi   = (const float*)d_in[3];
    const float* bw   = (const float*)d_in[4];
    const float* bb   = (const float*)d_in[5];
    const float* twm  = (const float*)d_in[6];
    const float* tbv  = (const float*)d_in[7];
    float* out = (float*)d_out;

    cudaFuncSetAttribute(k_fwd, cudaFuncAttributeMaxDynamicSharedMemorySize, FWD_SMEM);
    cudaFuncSetAttribute(k_out, cudaFuncAttributeMaxDynamicSharedMemorySize, OUT_SMEM);

    k_prep<<<1, 256>>>();
    k_proj<<<dim3(NB, 8), 256>>>(temb, twm, tbv);
    k_wt  <<<dim3(8, 128), dim3(32, 8)>>>(wr, wi);
    k_fwd <<<NB*NC, 128, FWD_SMEM>>>(x);
    k_mix <<<dim3(256, 4), 256>>>();
    k_invh<<<NB*NC, 256>>>();
    k_out <<<dim3(NB*NH, 2), 256, OUT_SMEM>>>(x, bw, bb, out);
}